// round 6
// baseline (speedup 1.0000x reference)
#include <cuda_runtime.h>
#include <cstdint>

#define HH 1024
#define WW 1024
#define HW (HH * WW)
#define KC 128
#define CAP 131072

// ---------------- device scratch (no allocations allowed) ----------------
__device__ int          g_idx_sem, g_idx_ctr, g_idx_offy, g_idx_offx, g_offx_shift;
__device__ int          g_cand_count;
__device__ unsigned int g_cand_bits[CAP];
__device__ int          g_cand_idx[CAP];
__device__ float2       g_centers[KC];              // (y, x) in rank order
__device__ int          g_nvalid;

struct Ptr4 { const void* p[4]; };

// ---------------- kernel 0: content-based input classification ----------------
//   class 2 (offsets): any sampled word has sign bit (N(0,4) ~half negative)
//   class 0 (sem):     all sampled words < 16 (ints 0..4)
//   class 1 (ctr_hmp): otherwise (positive floats in [0,1))
__global__ void detect_kernel(Ptr4 in, int n_eff) {
    __shared__ int cls[4];
    int w = threadIdx.x >> 5, lane = threadIdx.x & 31;
    if (w < n_eff) {
        const unsigned int* p = (const unsigned int*)in.p[w];
        unsigned v = p[lane * 32749];            // strided samples, max 1015219 < 2^20
        bool neg = v >= 0x80000000u;
        bool small = v < 16u;
        unsigned anyneg = __any_sync(0xffffffffu, neg);
        unsigned allsml = __all_sync(0xffffffffu, small);
        if (lane == 0) cls[w] = anyneg ? 2 : (allsml ? 0 : 1);
    }
    __syncthreads();
    if (threadIdx.x == 0) {
        int se = -1, ct = -1, o1 = -1, o2 = -1;
        for (int i = 0; i < n_eff && i < 4; i++) {
            if (cls[i] == 0)      { if (se < 0) se = i; }
            else if (cls[i] == 1) { if (ct < 0) ct = i; }
            else                  { if (o1 < 0) o1 = i; else if (o2 < 0) o2 = i; }
        }
        if (se < 0) se = 0;                      // defensive fallbacks
        if (ct < 0) ct = (se == 0) ? 1 : 0;
        if (o1 < 0) o1 = (n_eff > 2) ? 2 : ct;
        g_idx_sem  = se;
        g_idx_ctr  = ct;
        g_idx_offy = o1;
        g_idx_offx = (o2 >= 0) ? o2 : o1;        // separate x array if present
        g_offx_shift = (o2 >= 0) ? 0 : HW;       // else x channel at +HW
        g_cand_count = 0;
    }
}

// ---------------- kernel 1: 7x7 NMS, block-aggregated candidate append ----------------
__global__ void nms_kernel(Ptr4 in) {
    const float* __restrict__ ctr = (const float*)in.p[g_idx_ctr];
    __shared__ int s_cnt, s_base;
    if (threadIdx.x == 0) s_cnt = 0;
    __syncthreads();

    int idx = blockIdx.x * blockDim.x + threadIdx.x;
    int y = idx >> 10, x = idx & 1023;
    float v = ctr[idx];
    bool surv = v > 0.1f;                // threshold; <=0.1 -> -1, never a local max
    if (surv) {
        for (int dy = -3; dy <= 3 && surv; dy++) {
            int yy = y + dy;
            if ((unsigned)yy >= HH) continue;
            const float* __restrict__ row = ctr + yy * WW;
            for (int dx = -3; dx <= 3; dx++) {
                int xx = x + dx;
                if ((unsigned)xx >= WW) continue;
                if (row[xx] > v) { surv = false; break; }   // strictly greater kills; ties survive
            }
        }
    }
    int lp = -1;
    if (surv) lp = atomicAdd(&s_cnt, 1);
    __syncthreads();
    if (threadIdx.x == 0 && s_cnt > 0) s_base = atomicAdd(&g_cand_count, s_cnt);
    __syncthreads();
    if (surv) {
        int p = s_base + lp;
        if (p < CAP) { g_cand_bits[p] = __float_as_uint(v); g_cand_idx[p] = idx; }
    }
}

// ---------------- kernel 2: exact top-128 via 3-level radix select ----------------
__device__ __forceinline__ void find_cutoff(int* hist, int NB, int need,
                                            int* scanbuf, int* s_res) {
    int tid = threadIdx.x;
    int C = NB >> 10;
    int hi = NB - 1 - tid * C;
    int sum = 0;
    for (int j = 0; j < C; j++) sum += hist[hi - j];
    scanbuf[tid] = sum;
    __syncthreads();
    for (int off = 1; off < 1024; off <<= 1) {
        int v = (tid >= off) ? scanbuf[tid - off] : 0;
        __syncthreads();
        scanbuf[tid] += v;
        __syncthreads();
    }
    int incl = scanbuf[tid];
    int excl = incl - sum;
    if (excl < need && need <= incl) {
        int acc = excl;
        for (int j = 0; j < C; j++) {
            int b = hi - j;
            int h = hist[b];
            if (acc + h >= need) { s_res[0] = b; s_res[1] = acc; break; }
            acc += h;
        }
    }
    __syncthreads();
}

__global__ void __launch_bounds__(1024) select_kernel(float* __restrict__ out) {
    __shared__ int          hist[2048];
    __shared__ int          scanbuf[1024];
    __shared__ int          s_res[2];
    __shared__ unsigned int sel_bits[KC];
    __shared__ int          sel_idx[KC];
    __shared__ int          eq_idx[512];
    __shared__ int          s_nsel, s_neq;

    int tid = threadIdx.x;
    int n = min(g_cand_count, CAP);
    int m;
    if (tid == 0) { s_nsel = 0; s_neq = 0; }
    __syncthreads();

    if (n <= KC) {
        if (tid < n) { sel_bits[tid] = g_cand_bits[tid]; sel_idx[tid] = g_cand_idx[tid]; }
        m = n;
        __syncthreads();
    } else {
        // level 1: top 11 bits of float pattern (positive floats order-isomorphic to bits)
        for (int i = tid; i < 2048; i += 1024) hist[i] = 0;
        __syncthreads();
        for (int i = tid; i < n; i += 1024) atomicAdd(&hist[g_cand_bits[i] >> 21], 1);
        __syncthreads();
        find_cutoff(hist, 2048, KC, scanbuf, s_res);
        int b1 = s_res[0], above1 = s_res[1];
        __syncthreads();

        // level 2: next 11 bits within bucket b1
        for (int i = tid; i < 2048; i += 1024) hist[i] = 0;
        __syncthreads();
        for (int i = tid; i < n; i += 1024) {
            unsigned b = g_cand_bits[i];
            if ((b >> 21) == (unsigned)b1) atomicAdd(&hist[(b >> 10) & 2047], 1);
        }
        __syncthreads();
        find_cutoff(hist, 2048, KC - above1, scanbuf, s_res);
        int b2 = s_res[0];
        int above2 = above1 + s_res[1];
        unsigned pref2 = ((unsigned)b1 << 11) | (unsigned)b2;
        __syncthreads();

        // level 3: low 10 bits within (b1,b2)
        hist[tid] = 0;
        __syncthreads();
        for (int i = tid; i < n; i += 1024) {
            unsigned b = g_cand_bits[i];
            if ((b >> 10) == pref2) atomicAdd(&hist[b & 1023], 1);
        }
        __syncthreads();
        find_cutoff(hist, 1024, KC - above2, scanbuf, s_res);
        int aboveStrict = above2 + s_res[1];
        unsigned T = (pref2 << 10) | (unsigned)s_res[0];   // exact 128th value (bit pattern)
        __syncthreads();

        // collect: all strictly above T, plus (128 - aboveStrict) ties by smallest index
        for (int i = tid; i < n; i += 1024) {
            unsigned b = g_cand_bits[i];
            if (b > T) {
                int p = atomicAdd(&s_nsel, 1);
                sel_bits[p] = b; sel_idx[p] = g_cand_idx[i];
            } else if (b == T) {
                int p = atomicAdd(&s_neq, 1);
                if (p < 512) eq_idx[p] = g_cand_idx[i];
            }
        }
        __syncthreads();
        int r = KC - aboveStrict;
        int neq = min(s_neq, 512);
        if (tid < neq) {
            int my = eq_idx[tid];
            int rank = 0;
            for (int j = 0; j < neq; j++) rank += (eq_idx[j] < my);
            if (rank < r) { sel_bits[aboveStrict + rank] = T; sel_idx[aboveStrict + rank] = my; }
        }
        m = aboveStrict + min(r, neq);
        __syncthreads();
    }

    // rank the <=128 winners: descending value, ascending index (matches jax.lax.top_k)
    // OUTPUT IS FLOAT32 (Round-5 finding: harness compares a common float32 buffer;
    // int stores read back as denormals ~0 -> rel_err exactly 1.0 in rounds 1/3/4).
    if (tid < m) {
        unsigned mb = sel_bits[tid];
        int mi = sel_idx[tid];
        int rank = 0;
        for (int j = 0; j < m; j++) {
            unsigned ob = sel_bits[j];
            rank += (ob > mb) || (ob == mb && sel_idx[j] < mi);
        }
        int y = mi >> 10, x = mi & 1023;
        out[HW + 2 * rank]     = (float)y;
        out[HW + 2 * rank + 1] = (float)x;
        g_centers[rank] = make_float2((float)y, (float)x);
    } else if (tid < KC) {
        out[HW + 2 * tid]     = 0.0f;
        out[HW + 2 * tid + 1] = 0.0f;
        g_centers[tid] = make_float2(0.f, 0.f);
    }
    if (tid == 0) g_nvalid = m;
}

// ---------------- kernel 3: nearest-center assignment for thing pixels ----------------
__global__ void group_kernel(Ptr4 in, float* __restrict__ out) {
    const unsigned int* __restrict__ sem  = (const unsigned int*)in.p[g_idx_sem];
    const float* __restrict__        offy = (const float*)in.p[g_idx_offy];
    const float* __restrict__        offx = (const float*)in.p[g_idx_offx] + g_offx_shift;
    __shared__ float2 sc[KC];
    int tid = threadIdx.x;
    if (tid < KC) sc[tid] = g_centers[tid];
    __syncthreads();

    int idx = blockIdx.x * blockDim.x + tid;
    unsigned s = sem[idx];
    int m = g_nvalid;
    int res = 0;
    // thing classes 1,2 — accept int encoding (1,2) or float encoding (1.0f,2.0f)
    bool thing = (s == 1u) || (s == 2u) || (s == 0x3f800000u) || (s == 0x40000000u);
    if (thing && m > 0) {
        int y = idx >> 10, x = idx & 1023;
        // exact round-to-nearest ops, no FMA contraction -> bit-matches jax f32
        float py = __fadd_rn((float)y, offy[idx]);
        float px = __fadd_rn((float)x, offx[idx]);
        float best = __int_as_float(0x7f800000);   // +inf
        int bk = 0;
        #pragma unroll 4
        for (int k = 0; k < m; k++) {
            float2 c = sc[k];
            float dy = __fadd_rn(c.x, -py);
            float dx = __fadd_rn(c.y, -px);
            float d2 = __fadd_rn(__fmul_rn(dy, dy), __fmul_rn(dx, dx));
            if (d2 < best) { best = d2; bk = k; }  // strict < : first-index tie-break = argmin
        }
        res = bk + 1;
    }
    out[idx] = (float)res;                         // float32 output buffer
}

// ---------------- launch ----------------
extern "C" void kernel_launch(void* const* d_in, const int* in_sizes, int n_in,
                              void* d_out, int out_size) {
    (void)in_sizes; (void)out_size;
    Ptr4 in;
    int n_eff;
    if (n_in == 1) {
        const float* base = (const float*)d_in[0];
        in.p[0] = base; in.p[1] = base + HW; in.p[2] = base + 2 * HW; in.p[3] = base + 3 * HW;
        n_eff = 4;
    } else {
        for (int i = 0; i < 4; i++) in.p[i] = d_in[(i < n_in) ? i : 0];
        n_eff = n_in < 4 ? n_in : 4;
    }
    float* out = (float*)d_out;

    detect_kernel<<<1, 128>>>(in, n_eff);
    nms_kernel<<<HW / 256, 256>>>(in);
    select_kernel<<<1, 1024>>>(out);
    group_kernel<<<HW / 256, 256>>>(in, out);
}

// round 7
// speedup vs baseline: 1.4227x; 1.4227x over previous
#include <cuda_runtime.h>
#include <cstdint>

#define HH 1024
#define WW 1024
#define HW (HH * WW)
#define KC 128
#define CAPB 131072
#define CAPA 32768
#define HI_THRESH 0.999f

// ---------------- device scratch (no allocations allowed) ----------------
__device__ int          g_idx_sem, g_idx_ctr, g_idx_offy, g_idx_offx, g_offx_shift;
__device__ int          g_cntA, g_cntB, g_nwork, g_nvalid;
__device__ float        g_rowmax[HW];               // horizontal 7-max scratch
__device__ unsigned int g_bitsA[CAPA];              // high-score candidates (>HI_THRESH)
__device__ int          g_idxA[CAPA];
__device__ unsigned int g_bitsB[CAPB];              // all NMS survivors (fallback)
__device__ int          g_idxB[CAPB];
__device__ int          g_work[HW];                 // thing-pixel worklist
__device__ float2       g_centers[KC];              // (y, x) in rank order

struct Ptr4 { const void* p[4]; };

// ---------------- kernel 0: content-based input classification ----------------
__global__ void detect_kernel(Ptr4 in, int n_eff) {
    __shared__ int cls[4];
    int w = threadIdx.x >> 5, lane = threadIdx.x & 31;
    if (w < n_eff) {
        const unsigned int* p = (const unsigned int*)in.p[w];
        unsigned v = p[lane * 32749];
        bool neg = v >= 0x80000000u;
        bool small = v < 16u;
        unsigned anyneg = __any_sync(0xffffffffu, neg);
        unsigned allsml = __all_sync(0xffffffffu, small);
        if (lane == 0) cls[w] = anyneg ? 2 : (allsml ? 0 : 1);
    }
    __syncthreads();
    if (threadIdx.x == 0) {
        int se = -1, ct = -1, o1 = -1, o2 = -1;
        for (int i = 0; i < n_eff && i < 4; i++) {
            if (cls[i] == 0)      { if (se < 0) se = i; }
            else if (cls[i] == 1) { if (ct < 0) ct = i; }
            else                  { if (o1 < 0) o1 = i; else if (o2 < 0) o2 = i; }
        }
        if (se < 0) se = 0;
        if (ct < 0) ct = (se == 0) ? 1 : 0;
        if (o1 < 0) o1 = (n_eff > 2) ? 2 : ct;
        g_idx_sem  = se;
        g_idx_ctr  = ct;
        g_idx_offy = o1;
        g_idx_offx = (o2 >= 0) ? o2 : o1;
        g_offx_shift = (o2 >= 0) ? 0 : HW;
        g_cntA = 0; g_cntB = 0; g_nwork = 0;
    }
}

// ---------------- kernel 1a: horizontal 7-max (separable NMS, pass 1) ----------------
__global__ void rowmax_kernel(Ptr4 in) {
    const float* __restrict__ ctr = (const float*)in.p[g_idx_ctr];
    int idx = blockIdx.x * blockDim.x + threadIdx.x;
    int x = idx & 1023;
    float m = ctr[idx];
    int lo = (x >= 3) ? -3 : -x;
    int hi = (x <= 1020) ? 3 : 1023 - x;
    for (int d = lo; d <= hi; d++) m = fmaxf(m, ctr[idx + d]);
    g_rowmax[idx] = m;
}

// ---------------- kernel 1b: vertical 7-max + survivor append (pass 2) ----------------
// survivor <=> v > 0.1 && v == max7x7(raw): pooled >= v always, and neighbors <=0.1
// are mapped to -1 by the reference threshold so they can never beat v > 0.1.
__global__ void nmsv_kernel(Ptr4 in) {
    const float* __restrict__ ctr = (const float*)in.p[g_idx_ctr];
    __shared__ int sA, sB, bA, bB;
    if (threadIdx.x == 0) { sA = 0; sB = 0; }
    __syncthreads();

    int idx = blockIdx.x * blockDim.x + threadIdx.x;
    int y = idx >> 10, x = idx & 1023;
    float v = ctr[idx];
    bool surv = false, hicand = false;
    if (v > 0.1f) {
        float p = g_rowmax[idx];
        int ylo = (y >= 3) ? y - 3 : 0;
        int yhi = (y <= 1020) ? y + 3 : 1023;
        for (int yy = ylo; yy <= yhi; yy++) p = fmaxf(p, g_rowmax[yy * WW + x]);
        surv = (v == p);
        hicand = surv && (v > HI_THRESH);
    }
    int lB = surv   ? atomicAdd(&sB, 1) : -1;
    int lA = hicand ? atomicAdd(&sA, 1) : -1;
    __syncthreads();
    if (threadIdx.x == 0) {
        if (sB > 0) bB = atomicAdd(&g_cntB, sB);
        if (sA > 0) bA = atomicAdd(&g_cntA, sA);
    }
    __syncthreads();
    if (surv) {
        int p = bB + lB;
        if (p < CAPB) { g_bitsB[p] = __float_as_uint(v); g_idxB[p] = idx; }
    }
    if (hicand) {
        int p = bA + lA;
        if (p < CAPA) { g_bitsA[p] = __float_as_uint(v); g_idxA[p] = idx; }
    }
}

// ---------------- kernel 2: zero output map + compact thing-pixel worklist ----------------
__global__ void compact_kernel(Ptr4 in, float* __restrict__ out) {
    const unsigned int* __restrict__ sem = (const unsigned int*)in.p[g_idx_sem];
    __shared__ int s_cnt, s_base;
    if (threadIdx.x == 0) s_cnt = 0;
    __syncthreads();
    int idx = blockIdx.x * blockDim.x + threadIdx.x;
    unsigned s = sem[idx];
    out[idx] = 0.0f;                                  // default id (non-thing / no-center)
    bool thing = (s == 1u) || (s == 2u) || (s == 0x3f800000u) || (s == 0x40000000u);
    int lp = thing ? atomicAdd(&s_cnt, 1) : -1;
    __syncthreads();
    if (threadIdx.x == 0 && s_cnt > 0) s_base = atomicAdd(&g_nwork, s_cnt);
    __syncthreads();
    if (thing) g_work[s_base + lp] = idx;
}

// ---------------- kernel 3: exact top-128 via 3-level radix select ----------------
// suffix-sum cutoff search with 2-sync warp-shuffle scan (replaces 20-sync Hillis-Steele)
__device__ __forceinline__ void find_cutoff(const int* hist, int NB, int need,
                                            int* s_warp, int* s_res) {
    int tid = threadIdx.x, lane = tid & 31, wrp = tid >> 5;
    int C = NB >> 10;
    int hi = NB - 1 - tid * C;
    int sum = 0;
    for (int j = 0; j < C; j++) sum += hist[hi - j];
    int incl = sum;
    for (int o = 1; o < 32; o <<= 1) {
        int t = __shfl_up_sync(0xffffffffu, incl, o);
        if (lane >= o) incl += t;
    }
    if (lane == 31) s_warp[wrp] = incl;
    __syncthreads();
    if (wrp == 0) {
        int w = s_warp[lane];
        for (int o = 1; o < 32; o <<= 1) {
            int t = __shfl_up_sync(0xffffffffu, w, o);
            if (lane >= o) w += t;
        }
        s_warp[lane] = w;
    }
    __syncthreads();
    int base = wrp ? s_warp[wrp - 1] : 0;
    incl += base;
    int excl = incl - sum;
    if (excl < need && need <= incl) {
        int acc = excl;
        for (int j = 0; j < C; j++) {
            int b = hi - j;
            int h = hist[b];
            if (acc + h >= need) { s_res[0] = b; s_res[1] = acc; break; }
            acc += h;
        }
    }
    __syncthreads();
}

__global__ void __launch_bounds__(1024) select_kernel(float* __restrict__ out) {
    __shared__ int          hist[2048];
    __shared__ int          s_warp[32];
    __shared__ int          s_res[2];
    __shared__ unsigned int sel_bits[KC];
    __shared__ int          sel_idx[KC];
    __shared__ int          eq_idx[512];
    __shared__ int          s_nsel, s_neq;

    int tid = threadIdx.x;
    // fast path: if >=128 candidates exceed HI_THRESH, the exact top-128 is a
    // subset of list A (~1k entries) -> all passes run over A instead of ~21k.
    int nA = g_cntA, nB = min(g_cntB, CAPB);
    const unsigned int* bits;
    const int* idxs;
    int n;
    if (nA >= KC && nA <= CAPA) { bits = g_bitsA; idxs = g_idxA; n = nA; }
    else                        { bits = g_bitsB; idxs = g_idxB; n = nB; }

    int m;
    if (tid == 0) { s_nsel = 0; s_neq = 0; }
    __syncthreads();

    if (n <= KC) {
        if (tid < n) { sel_bits[tid] = bits[tid]; sel_idx[tid] = idxs[tid]; }
        m = n;
        __syncthreads();
    } else {
        // level 1: top 11 bits (positive floats order-isomorphic to their bits)
        for (int i = tid; i < 2048; i += 1024) hist[i] = 0;
        __syncthreads();
        for (int i = tid; i < n; i += 1024) atomicAdd(&hist[bits[i] >> 21], 1);
        __syncthreads();
        find_cutoff(hist, 2048, KC, s_warp, s_res);
        int b1 = s_res[0], above1 = s_res[1];
        __syncthreads();

        // level 2: next 11 bits within bucket b1
        for (int i = tid; i < 2048; i += 1024) hist[i] = 0;
        __syncthreads();
        for (int i = tid; i < n; i += 1024) {
            unsigned b = bits[i];
            if ((b >> 21) == (unsigned)b1) atomicAdd(&hist[(b >> 10) & 2047], 1);
        }
        __syncthreads();
        find_cutoff(hist, 2048, KC - above1, s_warp, s_res);
        int b2 = s_res[0];
        int above2 = above1 + s_res[1];
        unsigned pref2 = ((unsigned)b1 << 11) | (unsigned)b2;
        __syncthreads();

        // level 3: low 10 bits within (b1,b2)
        if (tid < 1024) hist[tid] = 0;
        __syncthreads();
        for (int i = tid; i < n; i += 1024) {
            unsigned b = bits[i];
            if ((b >> 10) == pref2) atomicAdd(&hist[b & 1023], 1);
        }
        __syncthreads();
        find_cutoff(hist, 1024, KC - above2, s_warp, s_res);
        int aboveStrict = above2 + s_res[1];
        unsigned T = (pref2 << 10) | (unsigned)s_res[0];   // exact 128th value bits
        __syncthreads();

        // collect strictly-above + ties by smallest index (jax.lax.top_k order)
        for (int i = tid; i < n; i += 1024) {
            unsigned b = bits[i];
            if (b > T) {
                int p = atomicAdd(&s_nsel, 1);
                sel_bits[p] = b; sel_idx[p] = idxs[i];
            } else if (b == T) {
                int p = atomicAdd(&s_neq, 1);
                if (p < 512) eq_idx[p] = idxs[i];
            }
        }
        __syncthreads();
        int r = KC - aboveStrict;
        int neq = min(s_neq, 512);
        if (tid < neq) {
            int my = eq_idx[tid];
            int rank = 0;
            for (int j = 0; j < neq; j++) rank += (eq_idx[j] < my);
            if (rank < r) { sel_bits[aboveStrict + rank] = T; sel_idx[aboveStrict + rank] = my; }
        }
        m = aboveStrict + min(r, neq);
        __syncthreads();
    }

    // rank winners: descending value, ascending index; float32 output buffer
    if (tid < m) {
        unsigned mb = sel_bits[tid];
        int mi = sel_idx[tid];
        int rank = 0;
        for (int j = 0; j < m; j++) {
            unsigned ob = sel_bits[j];
            rank += (ob > mb) || (ob == mb && sel_idx[j] < mi);
        }
        int y = mi >> 10, x = mi & 1023;
        out[HW + 2 * rank]     = (float)y;
        out[HW + 2 * rank + 1] = (float)x;
        g_centers[rank] = make_float2((float)y, (float)x);
    } else if (tid < KC) {
        out[HW + 2 * tid]     = 0.0f;
        out[HW + 2 * tid + 1] = 0.0f;
        g_centers[tid] = make_float2(0.f, 0.f);
    }
    if (tid == 0) g_nvalid = m;
}

// ---------------- kernel 4: nearest-center argmin over compacted worklist ----------------
// 2 pixels per thread share each center's LDS.64; strict-RN non-FMA math bit-matches jax.
__global__ void group_kernel(Ptr4 in, float* __restrict__ out) {
    const float* __restrict__ offy = (const float*)in.p[g_idx_offy];
    const float* __restrict__ offx = (const float*)in.p[g_idx_offx] + g_offx_shift;
    __shared__ float2 sc[KC];
    int tid = threadIdx.x;
    if (tid < KC) sc[tid] = g_centers[tid];
    __syncthreads();

    int m = g_nvalid;
    if (m == 0) return;                       // any_center false -> map stays all zero
    int N = g_nwork;
    int stride = gridDim.x * blockDim.x * 2;
    for (int base = (blockIdx.x * blockDim.x + tid) * 2; base < N; base += stride) {
        int i0 = g_work[base];
        int i1 = (base + 1 < N) ? g_work[base + 1] : i0;
        float npy0 = -__fadd_rn((float)(i0 >> 10), offy[i0]);
        float npx0 = -__fadd_rn((float)(i0 & 1023), offx[i0]);
        float npy1 = -__fadd_rn((float)(i1 >> 10), offy[i1]);
        float npx1 = -__fadd_rn((float)(i1 & 1023), offx[i1]);
        float best0 = __int_as_float(0x7f800000), best1 = best0;
        int k0 = 0, k1 = 0;
        #pragma unroll 4
        for (int k = 0; k < m; k++) {
            float2 c = sc[k];
            float dy0 = __fadd_rn(c.x, npy0);
            float dx0 = __fadd_rn(c.y, npx0);
            float d0  = __fadd_rn(__fmul_rn(dy0, dy0), __fmul_rn(dx0, dx0));
            float dy1 = __fadd_rn(c.x, npy1);
            float dx1 = __fadd_rn(c.y, npx1);
            float d1  = __fadd_rn(__fmul_rn(dy1, dy1), __fmul_rn(dx1, dx1));
            if (d0 < best0) { best0 = d0; k0 = k; }   // strict <: first-index tie-break
            if (d1 < best1) { best1 = d1; k1 = k; }
        }
        out[i0] = (float)(k0 + 1);
        out[i1] = (float)(k1 + 1);
    }
}

// ---------------- launch ----------------
extern "C" void kernel_launch(void* const* d_in, const int* in_sizes, int n_in,
                              void* d_out, int out_size) {
    (void)in_sizes; (void)out_size;
    Ptr4 in;
    int n_eff;
    if (n_in == 1) {
        const float* base = (const float*)d_in[0];
        in.p[0] = base; in.p[1] = base + HW; in.p[2] = base + 2 * HW; in.p[3] = base + 3 * HW;
        n_eff = 4;
    } else {
        for (int i = 0; i < 4; i++) in.p[i] = d_in[(i < n_in) ? i : 0];
        n_eff = n_in < 4 ? n_in : 4;
    }
    float* out = (float*)d_out;

    detect_kernel <<<1, 128>>>(in, n_eff);
    rowmax_kernel <<<HW / 256, 256>>>(in);
    nmsv_kernel   <<<HW / 256, 256>>>(in);
    compact_kernel<<<HW / 256, 256>>>(in, out);
    select_kernel <<<1, 1024>>>(out);
    group_kernel  <<<1024, 256>>>(in, out);
}